// round 6
// baseline (speedup 1.0000x reference)
#include <cuda_runtime.h>
#include <cstdint>
#include <math.h>

#define BB   32
#define SEQ  577
#define SEQP 640
#define CH   1024
#define NH   16
#define HD   64
#define HIDN 4096
#define MTOK (BB*SEQ)      // 18464 tokens
#define NBH  (BB*NH)       // 512 (batch*heads)

// ---------------- static scratch (no allocations allowed) ----------------
__device__ float  g_maxabs[4];
__device__ __align__(16) int8_t g_wqkv [3*CH*CH];
__device__ __align__(16) int8_t g_wproj[CH*CH];
__device__ __align__(16) int8_t g_wfc1 [HIDN*CH];
__device__ __align__(16) int8_t g_wfc2 [CH*HIDN];
__device__ __align__(16) int8_t g_a1[(size_t)MTOK*CH];
__device__ __align__(16) int8_t g_ao[(size_t)MTOK*CH];
__device__ __align__(16) int8_t g_a2[(size_t)MTOK*CH];
__device__ __align__(16) int8_t g_a3[(size_t)MTOK*HIDN];
__device__ float  g_q [(size_t)NBH*SEQ*HD];   // fl(q15/15) floats (bit-identical to R4)
__device__ float  g_kk[(size_t)NBH*SEQ*HD];
__device__ __align__(16) int8_t g_vth[(size_t)NBH*HD*SEQP];   // v15 hi plane, [bh][d][n]
__device__ __align__(16) int8_t g_vtl[(size_t)NBH*HD*SEQP];   // v15 lo plane
__device__ float  g_x1[(size_t)MTOK*CH];

// ---------------- weight quantization ----------------
__global__ void k_reset() { if (threadIdx.x < 4) g_maxabs[threadIdx.x] = 0.f; }

__global__ void k_absmax(const float* __restrict__ w, int n, int idx) {
    float m = 0.f;
    for (int i = blockIdx.x * blockDim.x + threadIdx.x; i < n; i += gridDim.x * blockDim.x)
        m = fmaxf(m, fabsf(w[i]));
    #pragma unroll
    for (int o = 16; o; o >>= 1) m = fmaxf(m, __shfl_xor_sync(0xffffffffu, m, o));
    if ((threadIdx.x & 31) == 0) atomicMax((int*)&g_maxabs[idx], __float_as_int(m));
}

__global__ void k_quantw(const float* __restrict__ w, int8_t* __restrict__ dst, int n, int idx) {
    float T = tanhf(g_maxabs[idx]);
    for (int i = blockIdx.x * blockDim.x + threadIdx.x; i < n; i += gridDim.x * blockDim.x) {
        float wn = tanhf(w[i]) / T;
        int m = (int)rintf((0.5f * wn + 0.5f) * 15.0f);
        dst[i] = (int8_t)(2 * m - 15);
    }
}

// ---------------- LayerNorm + 4-bit activation quant ----------------
__global__ void k_ln_aq(const float* __restrict__ x, const float* __restrict__ g,
                        const float* __restrict__ bb, int8_t* __restrict__ out) {
    int t = blockIdx.x;
    int tid = threadIdx.x;
    const float* row = x + (size_t)t * CH;
    __shared__ float red[8];
    float v[4];
    float s = 0.f;
    #pragma unroll
    for (int i = 0; i < 4; i++) { v[i] = row[tid + i * 256]; s += v[i]; }
    #pragma unroll
    for (int o = 16; o; o >>= 1) s += __shfl_xor_sync(0xffffffffu, s, o);
    if ((tid & 31) == 0) red[tid >> 5] = s;
    __syncthreads();
    if (tid < 8) {
        float z = red[tid];
        #pragma unroll
        for (int o = 4; o; o >>= 1) z += __shfl_xor_sync(0xffu, z, o);
        if (tid == 0) red[0] = z;
    }
    __syncthreads();
    float mean = red[0] * (1.0f / CH);
    __syncthreads();
    float qq = 0.f;
    #pragma unroll
    for (int i = 0; i < 4; i++) { float d = v[i] - mean; qq += d * d; }
    #pragma unroll
    for (int o = 16; o; o >>= 1) qq += __shfl_xor_sync(0xffffffffu, qq, o);
    if ((tid & 31) == 0) red[tid >> 5] = qq;
    __syncthreads();
    if (tid < 8) {
        float z = red[tid];
        #pragma unroll
        for (int o = 4; o; o >>= 1) z += __shfl_xor_sync(0xffu, z, o);
        if (tid == 0) red[0] = z;
    }
    __syncthreads();
    float sd = sqrtf(red[0] * (1.0f / CH) + 1e-5f);
    #pragma unroll
    for (int i = 0; i < 4; i++) {
        int c = tid + i * 256;
        float h = (v[i] - mean) / sd * g[c] + bb[c];
        out[(size_t)t * CH + c] = (int8_t)rintf(fminf(fmaxf(h, 0.f), 1.f) * 15.0f);
    }
}

// ---------------- mma helpers ----------------
__device__ __forceinline__ void ldsm4(uint32_t& r0, uint32_t& r1, uint32_t& r2, uint32_t& r3,
                                      const void* p) {
    uint32_t a = (uint32_t)__cvta_generic_to_shared(p);
    asm volatile("ldmatrix.sync.aligned.m8n8.x4.shared.b16 {%0,%1,%2,%3}, [%4];"
                 : "=r"(r0), "=r"(r1), "=r"(r2), "=r"(r3) : "r"(a));
}

__device__ __forceinline__ void imma(int* c, const uint32_t* a, const uint32_t* b) {
    asm volatile("mma.sync.aligned.m16n8k32.row.col.s32.s8.s8.s32 "
                 "{%0,%1,%2,%3},{%4,%5,%6,%7},{%8,%9},{%0,%1,%2,%3};"
                 : "+r"(c[0]), "+r"(c[1]), "+r"(c[2]), "+r"(c[3])
                 : "r"(a[0]), "r"(a[1]), "r"(a[2]), "r"(a[3]), "r"(b[0]), "r"(b[1]));
}

// packed fp32x2 fma: per-component IEEE rn => bit-identical to two scalar FFMA chains
__device__ __forceinline__ void fma2(unsigned long long& acc,
                                     unsigned long long a, unsigned long long b) {
    asm("fma.rn.f32x2 %0, %1, %2, %0;" : "+l"(acc) : "l"(a), "l"(b));
}
__device__ __forceinline__ unsigned long long pack2(float x, float y) {
    unsigned long long r;
    asm("mov.b64 %0, {%1, %2};" : "=l"(r) : "r"(__float_as_uint(x)), "r"(__float_as_uint(y)));
    return r;
}
__device__ __forceinline__ void unpack2(float& x, float& y, unsigned long long v) {
    uint32_t a, b;
    asm("mov.b64 {%0, %1}, %2;" : "=r"(a), "=r"(b) : "l"(v));
    x = __uint_as_float(a); y = __uint_as_float(b);
}

// ---------------- int8 tensor-core GEMM (mma.sync.m16n8k32) ----------------
// MODE 0: qkv  -> q,k: fl(rint(acc/15))/15 floats ; v: v15 split hi/lo int8 transposed
// MODE 1: proj -> x + round(acc/15 + 15b)/15 into outf (x1)
// MODE 2: fc1  -> gelu(round(acc/15+15b)/15) -> aq int8 into outi
// MODE 3: fc2  -> x1 + round(7*round(acc/15+15b)/15)/7 into outf (d_out)
template<int MODE>
__global__ void __launch_bounds__(256, 2)
gemm_mma(const int8_t* __restrict__ A, const int8_t* __restrict__ W,
         int Mdim, int K,
         const float* __restrict__ bias, const float* __restrict__ resid,
         float* __restrict__ outf, int8_t* __restrict__ outi) {
    __shared__ __align__(16) int8_t sA[128][80];
    __shared__ __align__(16) int8_t sB[128][80];

    const int tid  = threadIdx.x;
    const int lane = tid & 31;
    const int w    = tid >> 5;
    const int wm   = w >> 2;
    const int wn   = w & 3;
    const int mbase = blockIdx.y * 128;
    const int nbase = blockIdx.x * 128;

    const int r0c = tid >> 1, k0c = (tid & 1) * 2;
    int4 pa[2], pb[2];
    const int KT = K >> 6;

    {
        #pragma unroll
        for (int i = 0; i < 2; i++) {
            int kc = k0c + i;
            int gm = mbase + r0c;
            pa[i] = (gm < Mdim) ? *(const int4*)(A + (size_t)gm * K + kc * 16)
                                : make_int4(0, 0, 0, 0);
            pb[i] = *(const int4*)(W + (size_t)(nbase + r0c) * K + kc * 16);
        }
    }

    int acc[4][4][4];
    #pragma unroll
    for (int i = 0; i < 4; i++)
        #pragma unroll
        for (int j = 0; j < 4; j++)
            #pragma unroll
            for (int r = 0; r < 4; r++) acc[i][j][r] = 0;

    for (int kt = 0; kt < KT; kt++) {
        #pragma unroll
        for (int i = 0; i < 2; i++) {
            *(int4*)&sA[r0c][(k0c + i) * 16] = pa[i];
            *(int4*)&sB[r0c][(k0c + i) * 16] = pb[i];
        }
        __syncthreads();
        if (kt + 1 < KT) {
            int k0 = (kt + 1) * 64;
            #pragma unroll
            for (int i = 0; i < 2; i++) {
                int kc = k0c + i;
                int gm = mbase + r0c;
                pa[i] = (gm < Mdim) ? *(const int4*)(A + (size_t)gm * K + k0 + kc * 16)
                                    : make_int4(0, 0, 0, 0);
                pb[i] = *(const int4*)(W + (size_t)(nbase + r0c) * K + k0 + kc * 16);
            }
        }
        #pragma unroll
        for (int ks = 0; ks < 2; ks++) {
            const int kb = ks * 32;
            uint32_t af[4][4], bf[4][2];
            const int grp = lane >> 3, lr = lane & 7;
            #pragma unroll
            for (int mf = 0; mf < 4; mf++) {
                int row = wm * 64 + mf * 16 + lr + (grp & 1) * 8;
                int col = kb + (grp >> 1) * 16;
                ldsm4(af[mf][0], af[mf][1], af[mf][2], af[mf][3], &sA[row][col]);
            }
            #pragma unroll
            for (int h = 0; h < 2; h++) {
                int row = wn * 32 + h * 16 + lr + (grp >> 1) * 8;
                int col = kb + (grp & 1) * 16;
                uint32_t r0, r1, r2, r3;
                ldsm4(r0, r1, r2, r3, &sB[row][col]);
                bf[2*h][0] = r0; bf[2*h][1] = r1; bf[2*h+1][0] = r2; bf[2*h+1][1] = r3;
            }
            #pragma unroll
            for (int mf = 0; mf < 4; mf++)
                #pragma unroll
                for (int nf = 0; nf < 4; nf++)
                    imma(acc[mf][nf], af[mf], bf[nf]);
        }
        __syncthreads();
    }

    // epilogue
    #pragma unroll
    for (int mf = 0; mf < 4; mf++) {
        #pragma unroll
        for (int nf = 0; nf < 4; nf++) {
            #pragma unroll
            for (int r = 0; r < 4; r++) {
                int m = mbase + wm * 64 + mf * 16 + (lane >> 2) + ((r & 2) ? 8 : 0);
                int f = nbase + wn * 32 + nf * 8 + (lane & 3) * 2 + (r & 1);
                if (m >= Mdim) continue;
                float a15 = (float)acc[mf][nf][r] / 15.0f;   // exact int -> margin >= 1/30
                if (MODE == 0) {
                    int p = f >> 10, rem = f & 1023, h = rem >> 6, d = rem & 63;
                    int b = m / SEQ, n = m - b * SEQ;
                    int bh = b * NH + h;
                    if (p == 2) {
                        int v15 = (int)rintf(a15);
                        int hi = (v15 + 64) >> 7;            // floor div
                        int lo = v15 - (hi << 7);            // [-64,63]
                        size_t o = ((size_t)bh * HD + d) * SEQP + n;
                        g_vth[o] = (int8_t)hi; g_vtl[o] = (int8_t)lo;
                    } else {
                        float fv = rintf(a15) / 15.0f;       // bit-identical to R4 path
                        size_t o = ((size_t)bh * SEQ + n) * HD + d;
                        (p == 0 ? g_q : g_kk)[o] = fv;
                    }
                } else if (MODE == 1) {
                    float fv = rintf(a15 + 15.0f * bias[f]) / 15.0f;
                    outf[(size_t)m * CH + f] = resid[(size_t)m * CH + f] + fv;
                } else if (MODE == 2) {
                    float u = rintf(a15 + 15.0f * bias[f]) / 15.0f;
                    float ge = 0.5f * u * (1.0f + erff(u * 0.70710678118654752f));
                    outi[(size_t)m * HIDN + f] = (int8_t)rintf(fminf(fmaxf(ge, 0.f), 1.f) * 15.0f);
                } else {
                    float u = rintf(a15 + 15.0f * bias[f]) / 15.0f;
                    float y2 = rintf(u * 7.0f) / 7.0f;
                    outf[(size_t)m * CH + f] = resid[(size_t)m * CH + f] + y2;
                }
            }
        }
    }
}

// ---------------- fused attention (bit-identical S + softmax to R4; exact int av) ---
#define SW 592     // sS float row stride
#define PW 656     // pS byte row stride
#define QSTR 65
#define KSTR 66
#define SQ_BYTES  (64*QSTR*4)                 // 16640
#define ATT_B_OFF (64*SW*4)                   // 151552
#define ATT_SMEM  (64*SW*4 + 64*PW + 2*64*80) // 151552 + 41984 + 10240 = 203776

__global__ void __launch_bounds__(256) k_attn() {
    extern __shared__ __align__(16) int8_t smem[];
    float*  sS  = (float*)smem;                         // [64][SW]
    int8_t* B   = smem + ATT_B_OFF;
    float*  sQ  = (float*)B;                            // [64][QSTR]  (phase 1 only)
    float*  sKt = (float*)(B + SQ_BYTES);               // [64 d][KSTR m] (phase 1 only)
    int8_t* pS  = B;                                    // [64][PW]    (phase 2+)
    int8_t* sV  = B + 64 * PW;                          // [2][64][80] (phase 3)
    __shared__ float red[8];

    const int bh = blockIdx.y;
    const int n0 = blockIdx.x * 64;
    const int tid = threadIdx.x, lane = tid & 31, w = tid >> 5;
    const int tx = tid & 15, ty = tid >> 4;

    // load q tile (floats, zero-padded rows)
    for (int i = tid; i < 4096; i += 256) {
        int r = i >> 6, d = i & 63;
        int gn = n0 + r;
        sQ[r * QSTR + d] = (gn < SEQ) ? g_q[((size_t)bh * SEQ + gn) * HD + d] : 0.f;
    }
    __syncthreads();

    // ---- phase 1: S = q k^T * 0.125  (FFMA2, chains = R4 bit order) ----
    for (int t = 0; t < 10; t++) {
        int m0 = t * 64;
        for (int i = tid; i < 4096; i += 256) {
            int m = i >> 6, d = i & 63;
            int gm = m0 + m;
            sKt[d * KSTR + m] = (gm < SEQ) ? g_kk[((size_t)bh * SEQ + gm) * HD + d] : 0.f;
        }
        __syncthreads();
        unsigned long long acc[4][2];
        #pragma unroll
        for (int i = 0; i < 4; i++) { acc[i][0] = 0ULL; acc[i][1] = 0ULL; }
        #pragma unroll 8
        for (int d = 0; d < 64; d++) {
            const float* krow = &sKt[d * KSTR + tx * 4];
            unsigned long long B0 = *(const unsigned long long*)&krow[0];
            unsigned long long B1 = *(const unsigned long long*)&krow[2];
            #pragma unroll
            for (int i = 0; i < 4; i++) {
                float av = sQ[(ty * 4 + i) * QSTR + d];
                unsigned long long A = pack2(av, av);
                fma2(acc[i][0], A, B0);
                fma2(acc[i][1], A, B1);
            }
        }
        #pragma unroll
        for (int i = 0; i < 4; i++) {
            int row = ty * 4 + i;
            float s0, s1, s2, s3;
            unpack2(s0, s1, acc[i][0]);
            unpack2(s2, s3, acc[i][1]);
            int mb = m0 + tx * 4;
            if (mb + 0 < SEQ) sS[row * SW + mb + 0] = s0 * 0.125f;
            if (mb + 1 < SEQ) sS[row * SW + mb + 1] = s1 * 0.125f;
            if (mb + 2 < SEQ) sS[row * SW + mb + 2] = s2 * 0.125f;
            if (mb + 3 < SEQ) sS[row * SW + mb + 3] = s3 * 0.125f;
        }
        __syncthreads();
    }

    // ---- phase 2: softmax + 3-bit quant (bit-identical reduction to R4) ----
    for (int row = 0; row < 64; row++) {
        float mx = -1e30f;
        for (int i = tid; i < SEQ; i += 256) mx = fmaxf(mx, sS[row * SW + i]);
        #pragma unroll
        for (int o = 16; o; o >>= 1) mx = fmaxf(mx, __shfl_xor_sync(0xffffffffu, mx, o));
        if ((tid & 31) == 0) red[tid >> 5] = mx;
        __syncthreads();
        if (tid < 8) {
            float z = red[tid];
            #pragma unroll
            for (int o = 4; o; o >>= 1) z = fmaxf(z, __shfl_xor_sync(0xffu, z, o));
            if (tid == 0) red[0] = z;
        }
        __syncthreads();
        mx = red[0];
        __syncthreads();
        float s = 0.f;
        for (int i = tid; i < SEQ; i += 256) {
            float e = expf(sS[row * SW + i] - mx);
            sS[row * SW + i] = e;
            s += e;
        }
        #pragma unroll
        for (int o = 16; o; o >>= 1) s += __shfl_xor_sync(0xffffffffu, s, o);
        if ((tid & 31) == 0) red[tid >> 5] = s;
        __syncthreads();
        if (tid < 8) {
            float z = red[tid];
            #pragma unroll
            for (int o = 4; o; o >>= 1) z += __shfl_xor_sync(0xffu, z, o);
            if (tid == 0) red[0] = z;
        }
        __syncthreads();
        float tot = red[0];
        for (int i = tid; i < SEQP; i += 256) {
            int p7 = (i < SEQ) ? (int)rintf(7.0f * (sS[row * SW + i] / tot)) : 0;
            pS[row * PW + i] = (int8_t)p7;
        }
        __syncthreads();
    }

    // ---- phase 3: O = pS @ vT  (exact int8 IMMA; zero-flip epilogue) ----
    const int grp = lane >> 3, lr = lane & 7;
    const int wq = w >> 1;        // 0..3 : 16 q-rows
    const int wm = w & 1;         // 0..1 : 32 d-cols
    int oh[4][4] = {}, ol[4][4] = {};
    for (int t = 0; t < 20; t++) {
        int m0 = t * 32;
        {
            int i = tid;
            int mat = i >> 7, row = (i >> 1) & 63, c = i & 1;
            const int8_t* src = (mat ? g_vtl : g_vth) + ((size_t)bh * HD + row) * SEQP + m0 + c * 16;
            *(int4*)&sV[mat * 64 * 80 + row * 80 + c * 16] = *(const int4*)src;
        }
        __syncthreads();
        uint32_t af[4];
        {
            int row = wq * 16 + lr + (grp & 1) * 8;
            int col = m0 + (grp >> 1) * 16;
            ldsm4(af[0], af[1], af[2], af[3], &pS[row * PW + col]);
        }
        uint32_t bvh[4][2], bvl[4][2];
        #pragma unroll
        for (int h = 0; h < 2; h++) {
            int row = wm * 32 + h * 16 + lr + (grp >> 1) * 8;
            int col = (grp & 1) * 16;
            uint32_t r0, r1, r2, r3;
            ldsm4(r0, r1, r2, r3, &sV[row * 80 + col]);
            bvh[2*h][0] = r0; bvh[2*h][1] = r1; bvh[2*h+1][0] = r2; bvh[2*h+1][1] = r3;
            ldsm4(r0, r1, r2, r3, &sV[64 * 80 + row * 80 + col]);
            bvl[2*h][0] = r0; bvl[2*h][1] = r1; bvl[2*h+1][0] = r2; bvl[2*h+1][1] = r3;
        }
        #pragma unroll
        for (int nf = 0; nf < 4; nf++) {
            imma(oh[nf], af, bvh[nf]);
            imma(ol[nf], af, bvl[nf]);
        }
        __syncthreads();
    }
    const int b = bh >> 4, hh = bh & 15;
    #pragma unroll
    for (int nf = 0; nf < 4; nf++) {
        #pragma unroll
        for (int r = 0; r < 4; r++) {
            int n = n0 + wq * 16 + (lane >> 2) + ((r & 2) ? 8 : 0);
            int d = wm * 32 + nf * 8 + (lane & 3) * 2 + (r & 1);
            if (n < SEQ) {
                int S_int = (oh[nf][r] << 7) + ol[nf][r];           // exact sum p7*v15
                // 15*o = S_int/7: odd denominator => never a .5 tie (margin >= 1/14)
                int lvl = (int)rintf((float)S_int / 7.0f);
                lvl = lvl < 0 ? 0 : (lvl > 15 ? 15 : lvl);
                g_ao[((size_t)(b * SEQ + n)) * CH + hh * 64 + d] = (int8_t)lvl;
            }
        }
    }
}

// ---------------- launch ----------------
extern "C" void kernel_launch(void* const* d_in, const int* in_sizes, int n_in,
                              void* d_out, int out_size) {
    const float* x     = (const float*)d_in[0];
    const float* ln1w  = (const float*)d_in[1];
    const float* ln1b  = (const float*)d_in[2];
    const float* qkvw  = (const float*)d_in[3];
    const float* projw = (const float*)d_in[4];
    const float* projb = (const float*)d_in[5];
    const float* ln2w  = (const float*)d_in[6];
    const float* ln2b  = (const float*)d_in[7];
    const float* fc1w  = (const float*)d_in[8];
    const float* fc1b  = (const float*)d_in[9];
    const float* fc2w  = (const float*)d_in[10];
    const float* fc2b  = (const float*)d_in[11];

    void *p_wqkv, *p_wproj, *p_wfc1, *p_wfc2, *p_a1, *p_ao, *p_a2, *p_a3, *p_x1;
    cudaGetSymbolAddress(&p_wqkv,  g_wqkv);
    cudaGetSymbolAddress(&p_wproj, g_wproj);
    cudaGetSymbolAddress(&p_wfc1,  g_wfc1);
    cudaGetSymbolAddress(&p_wfc2,  g_wfc2);
    cudaGetSymbolAddress(&p_a1, g_a1);
    cudaGetSymbolAddress(&p_ao, g_ao);
    cudaGetSymbolAddress(&p_a2, g_a2);
    cudaGetSymbolAddress(&p_a3, g_a3);
    cudaGetSymbolAddress(&p_x1, g_x1);

    static int smem_set = 0;
    if (!smem_set) {
        cudaFuncSetAttribute(k_attn, cudaFuncAttributeMaxDynamicSharedMemorySize, ATT_SMEM);
        smem_set = 1;
    }

    const int MB = (MTOK + 127) / 128;   // 145
    k_reset<<<1, 32>>>();
    k_absmax<<<1024, 256>>>(qkvw,  3*CH*CH,  0);
    k_absmax<<<1024, 256>>>(projw, CH*CH,    1);
    k_absmax<<<1024, 256>>>(fc1w,  HIDN*CH,  2);
    k_absmax<<<1024, 256>>>(fc2w,  CH*HIDN,  3);
    k_quantw<<<2048, 256>>>(qkvw,  (int8_t*)p_wqkv,  3*CH*CH, 0);
    k_quantw<<<2048, 256>>>(projw, (int8_t*)p_wproj, CH*CH,   1);
    k_quantw<<<2048, 256>>>(fc1w,  (int8_t*)p_wfc1,  HIDN*CH, 2);
    k_quantw<<<2048, 256>>>(fc2w,  (int8_t*)p_wfc2,  CH*HIDN, 3);

    // attention branch
    k_ln_aq<<<MTOK, 256>>>(x, ln1w, ln1b, (int8_t*)p_a1);
    gemm_mma<0><<<dim3(24, MB), 256>>>((const int8_t*)p_a1, (const int8_t*)p_wqkv,
                                       MTOK, CH, nullptr, nullptr, nullptr, nullptr);
    k_attn<<<dim3(10, NBH), 256, ATT_SMEM>>>();
    gemm_mma<1><<<dim3(8, MB), 256>>>((const int8_t*)p_ao, (const int8_t*)p_wproj,
                                      MTOK, CH, projb, x, (float*)p_x1, nullptr);

    // MLP branch
    k_ln_aq<<<MTOK, 256>>>((const float*)p_x1, ln2w, ln2b, (int8_t*)p_a2);
    gemm_mma<2><<<dim3(32, MB), 256>>>((const int8_t*)p_a2, (const int8_t*)p_wfc1,
                                       MTOK, CH, fc1b, nullptr, nullptr, (int8_t*)p_a3);
    gemm_mma<3><<<dim3(8, MB), 256>>>((const int8_t*)p_a3, (const int8_t*)p_wfc2,
                                      MTOK, HIDN, fc2b, (const float*)p_x1, (float*)d_out, nullptr);
}

// round 7
// speedup vs baseline: 1.3849x; 1.3849x over previous
#include <cuda_runtime.h>
#include <cstdint>
#include <math.h>

#define BB   32
#define SEQ  577
#define SEQP 640
#define CH   1024
#define NH   16
#define HD   64
#define HIDN 4096
#define MTOK (BB*SEQ)      // 18464 tokens
#define NBH  (BB*NH)       // 512 (batch*heads)

// ---------------- static scratch (no allocations allowed) ----------------
__device__ float  g_maxabs[4];
__device__ __align__(16) int8_t g_wqkv [3*CH*CH];
__device__ __align__(16) int8_t g_wproj[CH*CH];
__device__ __align__(16) int8_t g_wfc1 [HIDN*CH];
__device__ __align__(16) int8_t g_wfc2 [CH*HIDN];
__device__ __align__(16) int8_t g_a1[(size_t)MTOK*CH];
__device__ __align__(16) int8_t g_ao[(size_t)MTOK*CH];
__device__ __align__(16) int8_t g_a2[(size_t)MTOK*CH];
__device__ __align__(16) int8_t g_a3[(size_t)MTOK*HIDN];
__device__ float  g_q [(size_t)NBH*SEQ*HD];   // fl(q15/15) floats (bit-identical to R4)
__device__ float  g_kk[(size_t)NBH*SEQ*HD];
__device__ __align__(16) int8_t g_vth[(size_t)NBH*HD*SEQP];   // v15 hi plane, [bh][d][n]
__device__ __align__(16) int8_t g_vtl[(size_t)NBH*HD*SEQP];   // v15 lo plane
__device__ float  g_S [(size_t)NBH*SEQ*SEQ];                  // raw scores (softmax input)
__device__ __align__(16) int8_t g_pS[(size_t)NBH*SEQP*SEQP];  // 3-bit probs p7
__device__ float  g_x1[(size_t)MTOK*CH];

// ---------------- weight quantization ----------------
__global__ void k_reset() { if (threadIdx.x < 4) g_maxabs[threadIdx.x] = 0.f; }

__global__ void k_absmax(const float* __restrict__ w, int n, int idx) {
    float m = 0.f;
    for (int i = blockIdx.x * blockDim.x + threadIdx.x; i < n; i += gridDim.x * blockDim.x)
        m = fmaxf(m, fabsf(w[i]));
    #pragma unroll
    for (int o = 16; o; o >>= 1) m = fmaxf(m, __shfl_xor_sync(0xffffffffu, m, o));
    if ((threadIdx.x & 31) == 0) atomicMax((int*)&g_maxabs[idx], __float_as_int(m));
}

__global__ void k_quantw(const float* __restrict__ w, int8_t* __restrict__ dst, int n, int idx) {
    float T = tanhf(g_maxabs[idx]);
    for (int i = blockIdx.x * blockDim.x + threadIdx.x; i < n; i += gridDim.x * blockDim.x) {
        float wn = tanhf(w[i]) / T;
        int m = (int)rintf((0.5f * wn + 0.5f) * 15.0f);
        dst[i] = (int8_t)(2 * m - 15);
    }
}

// ---------------- LayerNorm + 4-bit activation quant ----------------
__global__ void k_ln_aq(const float* __restrict__ x, const float* __restrict__ g,
                        const float* __restrict__ bb, int8_t* __restrict__ out) {
    int t = blockIdx.x;
    int tid = threadIdx.x;
    const float* row = x + (size_t)t * CH;
    __shared__ float red[8];
    float v[4];
    float s = 0.f;
    #pragma unroll
    for (int i = 0; i < 4; i++) { v[i] = row[tid + i * 256]; s += v[i]; }
    #pragma unroll
    for (int o = 16; o; o >>= 1) s += __shfl_xor_sync(0xffffffffu, s, o);
    if ((tid & 31) == 0) red[tid >> 5] = s;
    __syncthreads();
    if (tid < 8) {
        float z = red[tid];
        #pragma unroll
        for (int o = 4; o; o >>= 1) z += __shfl_xor_sync(0xffu, z, o);
        if (tid == 0) red[0] = z;
    }
    __syncthreads();
    float mean = red[0] * (1.0f / CH);
    __syncthreads();
    float qq = 0.f;
    #pragma unroll
    for (int i = 0; i < 4; i++) { float d = v[i] - mean; qq += d * d; }
    #pragma unroll
    for (int o = 16; o; o >>= 1) qq += __shfl_xor_sync(0xffffffffu, qq, o);
    if ((tid & 31) == 0) red[tid >> 5] = qq;
    __syncthreads();
    if (tid < 8) {
        float z = red[tid];
        #pragma unroll
        for (int o = 4; o; o >>= 1) z += __shfl_xor_sync(0xffu, z, o);
        if (tid == 0) red[0] = z;
    }
    __syncthreads();
    float sd = sqrtf(red[0] * (1.0f / CH) + 1e-5f);
    #pragma unroll
    for (int i = 0; i < 4; i++) {
        int c = tid + i * 256;
        float h = (v[i] - mean) / sd * g[c] + bb[c];
        out[(size_t)t * CH + c] = (int8_t)rintf(fminf(fmaxf(h, 0.f), 1.f) * 15.0f);
    }
}

// ---------------- mma helpers ----------------
__device__ __forceinline__ void ldsm4(uint32_t& r0, uint32_t& r1, uint32_t& r2, uint32_t& r3,
                                      const void* p) {
    uint32_t a = (uint32_t)__cvta_generic_to_shared(p);
    asm volatile("ldmatrix.sync.aligned.m8n8.x4.shared.b16 {%0,%1,%2,%3}, [%4];"
                 : "=r"(r0), "=r"(r1), "=r"(r2), "=r"(r3) : "r"(a));
}

__device__ __forceinline__ void imma(int* c, const uint32_t* a, const uint32_t* b) {
    asm volatile("mma.sync.aligned.m16n8k32.row.col.s32.s8.s8.s32 "
                 "{%0,%1,%2,%3},{%4,%5,%6,%7},{%8,%9},{%0,%1,%2,%3};"
                 : "+r"(c[0]), "+r"(c[1]), "+r"(c[2]), "+r"(c[3])
                 : "r"(a[0]), "r"(a[1]), "r"(a[2]), "r"(a[3]), "r"(b[0]), "r"(b[1]));
}

// packed fp32x2 fma: per-component IEEE rn => bit-identical to two scalar FFMA chains
__device__ __forceinline__ void fma2(unsigned long long& acc,
                                     unsigned long long a, unsigned long long b) {
    asm("fma.rn.f32x2 %0, %1, %2, %0;" : "+l"(acc) : "l"(a), "l"(b));
}
__device__ __forceinline__ unsigned long long pack2(float x, float y) {
    unsigned long long r;
    asm("mov.b64 %0, {%1, %2};" : "=l"(r) : "r"(__float_as_uint(x)), "r"(__float_as_uint(y)));
    return r;
}
__device__ __forceinline__ void unpack2(float& x, float& y, unsigned long long v) {
    uint32_t a, b;
    asm("mov.b64 {%0, %1}, %2;" : "=r"(a), "=r"(b) : "l"(v));
    x = __uint_as_float(a); y = __uint_as_float(b);
}

// ---------------- int8 tensor-core GEMM (mma.sync.m16n8k32) ----------------
// MODE 0: qkv  -> q,k: fl(rint(acc/15))/15 floats ; v: v15 split hi/lo int8 transposed
// MODE 1: proj -> x + round(acc/15 + 15b)/15 into outf (x1)
// MODE 2: fc1  -> gelu(round(acc/15+15b)/15) -> aq int8 into outi
// MODE 3: fc2  -> x1 + round(7*round(acc/15+15b)/15)/7 into outf (d_out)
template<int MODE>
__global__ void __launch_bounds__(256, 2)
gemm_mma(const int8_t* __restrict__ A, const int8_t* __restrict__ W,
         int Mdim, int K,
         const float* __restrict__ bias, const float* __restrict__ resid,
         float* __restrict__ outf, int8_t* __restrict__ outi) {
    __shared__ __align__(16) int8_t sA[128][80];
    __shared__ __align__(16) int8_t sB[128][80];

    const int tid  = threadIdx.x;
    const int lane = tid & 31;
    const int w    = tid >> 5;
    const int wm   = w >> 2;
    const int wn   = w & 3;
    const int mbase = blockIdx.y * 128;
    const int nbase = blockIdx.x * 128;

    const int r0c = tid >> 1, k0c = (tid & 1) * 2;
    int4 pa[2], pb[2];
    const int KT = K >> 6;

    {
        #pragma unroll
        for (int i = 0; i < 2; i++) {
            int kc = k0c + i;
            int gm = mbase + r0c;
            pa[i] = (gm < Mdim) ? *(const int4*)(A + (size_t)gm * K + kc * 16)
                                : make_int4(0, 0, 0, 0);
            pb[i] = *(const int4*)(W + (size_t)(nbase + r0c) * K + kc * 16);
        }
    }

    int acc[4][4][4];
    #pragma unroll
    for (int i = 0; i < 4; i++)
        #pragma unroll
        for (int j = 0; j < 4; j++)
            #pragma unroll
            for (int r = 0; r < 4; r++) acc[i][j][r] = 0;

    for (int kt = 0; kt < KT; kt++) {
        #pragma unroll
        for (int i = 0; i < 2; i++) {
            *(int4*)&sA[r0c][(k0c + i) * 16] = pa[i];
            *(int4*)&sB[r0c][(k0c + i) * 16] = pb[i];
        }
        __syncthreads();
        if (kt + 1 < KT) {
            int k0 = (kt + 1) * 64;
            #pragma unroll
            for (int i = 0; i < 2; i++) {
                int kc = k0c + i;
                int gm = mbase + r0c;
                pa[i] = (gm < Mdim) ? *(const int4*)(A + (size_t)gm * K + k0 + kc * 16)
                                    : make_int4(0, 0, 0, 0);
                pb[i] = *(const int4*)(W + (size_t)(nbase + r0c) * K + k0 + kc * 16);
            }
        }
        #pragma unroll
        for (int ks = 0; ks < 2; ks++) {
            const int kb = ks * 32;
            uint32_t af[4][4], bf[4][2];
            const int grp = lane >> 3, lr = lane & 7;
            #pragma unroll
            for (int mf = 0; mf < 4; mf++) {
                int row = wm * 64 + mf * 16 + lr + (grp & 1) * 8;
                int col = kb + (grp >> 1) * 16;
                ldsm4(af[mf][0], af[mf][1], af[mf][2], af[mf][3], &sA[row][col]);
            }
            #pragma unroll
            for (int h = 0; h < 2; h++) {
                int row = wn * 32 + h * 16 + lr + (grp >> 1) * 8;
                int col = kb + (grp & 1) * 16;
                uint32_t r0, r1, r2, r3;
                ldsm4(r0, r1, r2, r3, &sB[row][col]);
                bf[2*h][0] = r0; bf[2*h][1] = r1; bf[2*h+1][0] = r2; bf[2*h+1][1] = r3;
            }
            #pragma unroll
            for (int mf = 0; mf < 4; mf++)
                #pragma unroll
                for (int nf = 0; nf < 4; nf++)
                    imma(acc[mf][nf], af[mf], bf[nf]);
        }
        __syncthreads();
    }

    // epilogue
    #pragma unroll
    for (int mf = 0; mf < 4; mf++) {
        #pragma unroll
        for (int nf = 0; nf < 4; nf++) {
            #pragma unroll
            for (int r = 0; r < 4; r++) {
                int m = mbase + wm * 64 + mf * 16 + (lane >> 2) + ((r & 2) ? 8 : 0);
                int f = nbase + wn * 32 + nf * 8 + (lane & 3) * 2 + (r & 1);
                if (m >= Mdim) continue;
                float a15 = (float)acc[mf][nf][r] / 15.0f;   // exact int -> margin >= 1/30
                if (MODE == 0) {
                    int p = f >> 10, rem = f & 1023, h = rem >> 6, d = rem & 63;
                    int b = m / SEQ, n = m - b * SEQ;
                    int bh = b * NH + h;
                    if (p == 2) {
                        int v15 = (int)rintf(a15);
                        int hi = (v15 + 64) >> 7;            // floor div
                        int lo = v15 - (hi << 7);            // [-64,63]
                        size_t o = ((size_t)bh * HD + d) * SEQP + n;
                        g_vth[o] = (int8_t)hi; g_vtl[o] = (int8_t)lo;
                    } else {
                        float fv = rintf(a15) / 15.0f;       // bit-identical to R4 path
                        size_t o = ((size_t)bh * SEQ + n) * HD + d;
                        (p == 0 ? g_q : g_kk)[o] = fv;
                    }
                } else if (MODE == 1) {
                    float fv = rintf(a15 + 15.0f * bias[f]) / 15.0f;
                    outf[(size_t)m * CH + f] = resid[(size_t)m * CH + f] + fv;
                } else if (MODE == 2) {
                    float u = rintf(a15 + 15.0f * bias[f]) / 15.0f;
                    float ge = 0.5f * u * (1.0f + erff(u * 0.70710678118654752f));
                    outi[(size_t)m * HIDN + f] = (int8_t)rintf(fminf(fmaxf(ge, 0.f), 1.f) * 15.0f);
                } else {
                    float u = rintf(a15 + 15.0f * bias[f]) / 15.0f;
                    float y2 = rintf(u * 7.0f) / 7.0f;
                    outf[(size_t)m * CH + f] = resid[(size_t)m * CH + f] + y2;
                }
            }
        }
    }
}

// ---------------- S = q k^T * 0.125 (FFMA2; chains bit-identical to R4) ----------------
__global__ void __launch_bounds__(256) k_qk2() {
    __shared__ float sQ[64][65];
    __shared__ float sKt[64][66];   // [d][m]
    const int bh = blockIdx.z;
    const int n0 = blockIdx.y * 64, m0 = blockIdx.x * 64;
    const int tid = threadIdx.x, tx = tid & 15, ty = tid >> 4;

    for (int i = tid; i < 4096; i += 256) {
        int r = i >> 6, d = i & 63;
        int gn = n0 + r;
        sQ[r][d] = (gn < SEQ) ? g_q[((size_t)bh * SEQ + gn) * HD + d] : 0.f;
        int gm = m0 + r;
        sKt[d][r] = (gm < SEQ) ? g_kk[((size_t)bh * SEQ + gm) * HD + d] : 0.f;
    }
    __syncthreads();

    unsigned long long acc[4][2];
    #pragma unroll
    for (int i = 0; i < 4; i++) { acc[i][0] = 0ULL; acc[i][1] = 0ULL; }
    #pragma unroll 8
    for (int d = 0; d < 64; d++) {
        const float* krow = &sKt[d][tx * 4];
        unsigned long long B0 = *(const unsigned long long*)&krow[0];
        unsigned long long B1 = *(const unsigned long long*)&krow[2];
        #pragma unroll
        for (int i = 0; i < 4; i++) {
            float av = sQ[ty * 4 + i][d];
            unsigned long long A = pack2(av, av);
            fma2(acc[i][0], A, B0);
            fma2(acc[i][1], A, B1);
        }
    }
    #pragma unroll
    for (int i = 0; i < 4; i++) {
        int n = n0 + ty * 4 + i;
        if (n >= SEQ) continue;
        float s0, s1, s2, s3;
        unpack2(s0, s1, acc[i][0]);
        unpack2(s2, s3, acc[i][1]);
        float* dst = g_S + ((size_t)bh * SEQ + n) * SEQ;
        int mb = m0 + tx * 4;
        if (mb + 0 < SEQ) dst[mb + 0] = s0 * 0.125f;
        if (mb + 1 < SEQ) dst[mb + 1] = s1 * 0.125f;
        if (mb + 2 < SEQ) dst[mb + 2] = s2 * 0.125f;
        if (mb + 3 < SEQ) dst[mb + 3] = s3 * 0.125f;
    }
}

// ---------------- softmax + 3-bit quant -> int8 p7 (reduction bit-identical to R4) ----
__global__ void k_softmax() {
    const int n = blockIdx.x, bh = blockIdx.y;
    const float* row = g_S + ((size_t)bh * SEQ + n) * SEQ;
    int8_t* prow = g_pS + ((size_t)bh * SEQP + n) * SEQP;
    __shared__ float buf[SEQ];
    __shared__ float red[8];
    const int tid = threadIdx.x;   // 256
    float mx = -1e30f;
    for (int i = tid; i < SEQ; i += 256) { float v = row[i]; buf[i] = v; mx = fmaxf(mx, v); }
    #pragma unroll
    for (int o = 16; o; o >>= 1) mx = fmaxf(mx, __shfl_xor_sync(0xffffffffu, mx, o));
    if ((tid & 31) == 0) red[tid >> 5] = mx;
    __syncthreads();
    if (tid < 8) {
        float z = red[tid];
        #pragma unroll
        for (int o = 4; o; o >>= 1) z = fmaxf(z, __shfl_xor_sync(0xffu, z, o));
        if (tid == 0) red[0] = z;
    }
    __syncthreads();
    mx = red[0];
    __syncthreads();
    float s = 0.f;
    for (int i = tid; i < SEQ; i += 256) { float e = expf(buf[i] - mx); buf[i] = e; s += e; }
    #pragma unroll
    for (int o = 16; o; o >>= 1) s += __shfl_xor_sync(0xffffffffu, s, o);
    if ((tid & 31) == 0) red[tid >> 5] = s;
    __syncthreads();
    if (tid < 8) {
        float z = red[tid];
        #pragma unroll
        for (int o = 4; o; o >>= 1) z += __shfl_xor_sync(0xffu, z, o);
        if (tid == 0) red[0] = z;
    }
    __syncthreads();
    float tot = red[0];
    for (int i = tid; i < SEQP; i += 256) {
        int p7 = (i < SEQ) ? (int)rintf(7.0f * (buf[i] / tot)) : 0;
        prow[i] = (int8_t)p7;
    }
}

// ---------------- O = p7 @ vT (exact int8 IMMA, fused _aq) ----------------
#define PW 656
#define AV_SMEM (64*PW + 2*64*80)   // 41984 + 10240 = 52224

__global__ void __launch_bounds__(256) k_av2() {
    extern __shared__ __align__(16) int8_t smem[];
    int8_t* pS = smem;              // [64][PW]
    int8_t* sV = smem + 64 * PW;    // [2][64][80]
    const int bh = blockIdx.y;
    const int n0 = blockIdx.x * 64;
    const int tid = threadIdx.x, lane = tid & 31, w = tid >> 5;
    const int grp = lane >> 3, lr = lane & 7;
    const int wq = w >> 1;          // 0..3 : 16 q-rows
    const int wm = w & 1;           // 0..1 : 32 d-cols

    // load p7 tile rows n0..n0+63 (cols 0..SEQP)
    for (int i = tid; i < 2560; i += 256) {
        int row = i / 40, c = i % 40;
        *(int4*)&pS[row * PW + c * 16] =
            *(const int4*)&g_pS[((size_t)bh * SEQP + n0 + row) * SEQP + c * 16];
    }
    __syncthreads();

    int oh[4][4] = {}, ol[4][4] = {};
    for (int t = 0; t < 20; t++) {
        int m0 = t * 32;
        {
            int i = tid;
            int mat = i >> 7, row = (i >> 1) & 63, c = i & 1;
            const int8_t* src = (mat ? g_vtl : g_vth) + ((size_t)bh * HD + row) * SEQP + m0 + c * 16;
            *(int4*)&sV[mat * 64 * 80 + row * 80 + c * 16] = *(const int4*)src;
        }
        __syncthreads();
        uint32_t af[4];
        {
            int row = wq * 16 + lr + (grp & 1) * 8;
            int col = m0 + (grp >> 1) * 16;
            ldsm4(af[0], af[1], af[2], af[3], &pS[row * PW + col]);
        }
        uint32_t bvh[4][2], bvl[4][2];
        #pragma unroll
        for (int h = 0; h < 2; h++) {
            int row = wm * 32 + h * 16 + lr + (grp >> 1) * 8;
            int col = (grp & 1) * 16;
            uint32_t r0, r1, r2, r3;
            ldsm4(r0, r1, r2, r3, &sV[row * 80 + col]);
            bvh[2*h][0] = r0; bvh[2*h][1] = r1; bvh[2*h+1][0] = r2; bvh[2*h+1][1] = r3;
            ldsm4(r0, r1, r2, r3, &sV[64 * 80 + row * 80 + col]);
            bvl[2*h][0] = r0; bvl[2*h][1] = r1; bvl[2*h+1][0] = r2; bvl[2*h+1][1] = r3;
        }
        #pragma unroll
        for (int nf = 0; nf < 4; nf++) {
            imma(oh[nf], af, bvh[nf]);
            imma(ol[nf], af, bvl[nf]);
        }
        __syncthreads();
    }
    const int b = bh >> 4, hh = bh & 15;
    #pragma unroll
    for (int nf = 0; nf < 4; nf++) {
        #pragma unroll
        for (int r = 0; r < 4; r++) {
            int n = n0 + wq * 16 + (lane >> 2) + ((r & 2) ? 8 : 0);
            int d = wm * 32 + nf * 8 + (lane & 3) * 2 + (r & 1);
            if (n < SEQ) {
                int S_int = (oh[nf][r] << 7) + ol[nf][r];   // exact sum p7*v15
                // 15*o = S_int/7: odd denominator => never a .5 tie
                int lvl = (int)rintf((float)S_int / 7.0f);
                lvl = lvl < 0 ? 0 : (lvl > 15 ? 15 : lvl);
                g_ao[((size_t)(b * SEQ + n)) * CH + hh * 64 + d] = (int8_t)lvl;
            }
        }
    }
}

// ---------------- launch ----------------
extern "C" void kernel_launch(void* const* d_in, const int* in_sizes, int n_in,
                              void* d_out, int out_size) {
    const float* x     = (const float*)d_in[0];
    const float* ln1w  = (const float*)d_in[1];
    const float* ln1b  = (const float*)d_in[2];
    const float* qkvw  = (const float*)d_in[3];
    const float* projw = (const float*)d_in[4];
    const float* projb = (const float*)d_in[5];
    const float* ln2w  = (const float*)d_in[6];
    const float* ln2b  = (const float*)d_in[7];
    const float* fc1w  = (const float*)d_in[8];
    const float* fc1b  = (const float*)d_in[9];
    const float* fc2w  = (const float*)d_in[10];
    const float* fc2b  = (const float*)d_in[11];

    void *p_wqkv, *p_wproj, *p_wfc1, *p_wfc2, *p_a1, *p_ao, *p_a2, *p_a3, *p_x1;
    cudaGetSymbolAddress(&p_wqkv,  g_wqkv);
    cudaGetSymbolAddress(&p_wproj, g_wproj);
    cudaGetSymbolAddress(&p_wfc1,  g_wfc1);
    cudaGetSymbolAddress(&p_wfc2,  g_wfc2);
    cudaGetSymbolAddress(&p_a1, g_a1);
    cudaGetSymbolAddress(&p_ao, g_ao);
    cudaGetSymbolAddress(&p_a2, g_a2);
    cudaGetSymbolAddress(&p_a3, g_a3);
    cudaGetSymbolAddress(&p_x1, g_x1);

    cudaFuncSetAttribute(k_av2, cudaFuncAttributeMaxDynamicSharedMemorySize, AV_SMEM);

    const int MB = (MTOK + 127) / 128;   // 145
    k_reset<<<1, 32>>>();
    k_absmax<<<1024, 256>>>(qkvw,  3*CH*CH,  0);
    k_absmax<<<1024, 256>>>(projw, CH*CH,    1);
    k_absmax<<<1024, 256>>>(fc1w,  HIDN*CH,  2);
    k_absmax<<<1024, 256>>>(fc2w,  CH*HIDN,  3);
    k_quantw<<<2048, 256>>>(qkvw,  (int8_t*)p_wqkv,  3*CH*CH, 0);
    k_quantw<<<2048, 256>>>(projw, (int8_t*)p_wproj, CH*CH,   1);
    k_quantw<<<2048, 256>>>(fc1w,  (int8_t*)p_wfc1,  HIDN*CH, 2);
    k_quantw<<<2048, 256>>>(fc2w,  (int8_t*)p_wfc2,  CH*HIDN, 3);

    // attention branch
    k_ln_aq<<<MTOK, 256>>>(x, ln1w, ln1b, (int8_t*)p_a1);
    gemm_mma<0><<<dim3(24, MB), 256>>>((const int8_t*)p_a1, (const int8_t*)p_wqkv,
                                       MTOK, CH, nullptr, nullptr, nullptr, nullptr);
    k_qk2<<<dim3(10, 10, NBH), 256>>>();
    k_softmax<<<dim3(SEQ, NBH), 256>>>();
    k_av2<<<dim3(10, NBH), 256, AV_SMEM>>>();
    gemm_mma<1><<<dim3(8, MB), 256>>>((const int8_t*)p_ao, (const int8_t*)p_wproj,
                                      MTOK, CH, projb, x, (float*)p_x1, nullptr);

    // MLP branch
    k_ln_aq<<<MTOK, 256>>>((const float*)p_x1, ln2w, ln2b, (int8_t*)p_a2);
    gemm_mma<2><<<dim3(32, MB), 256>>>((const int8_t*)p_a2, (const int8_t*)p_wfc1,
                                       MTOK, CH, fc1b, nullptr, nullptr, (int8_t*)p_a3);
    gemm_mma<3><<<dim3(8, MB), 256>>>((const int8_t*)p_a3, (const int8_t*)p_wfc2,
                                      MTOK, HIDN, fc2b, (const float*)p_x1, (float*)d_out, nullptr);
}